// round 1
// baseline (speedup 1.0000x reference)
#include <cuda_runtime.h>
#include <cstdint>

#define DEVINL __device__ __forceinline__

constexpr int kB = 4, kS = 2048, kD = 1024, kH = 16, kHD = 64;
constexpr int kM = kB * kS;  // 8192 rows for QKV GEMM

// Scratch: Q/K/V in [B, H, S, hd] layout (head-major for attention).
__device__ float g_q[(long long)kB * kH * kS * kHD];
__device__ float g_k[(long long)kB * kH * kS * kHD];
__device__ float g_v[(long long)kB * kH * kS * kHD];

DEVINL uint32_t smem_u32(const void* p) {
    return (uint32_t)__cvta_generic_to_shared(p);
}
DEVINL void cp_async16(uint32_t dst, const void* src) {
    asm volatile("cp.async.cg.shared.global [%0], [%1], 16;\n" ::"r"(dst), "l"(src));
}
DEVINL void cp_commit() { asm volatile("cp.async.commit_group;\n" ::: "memory"); }
DEVINL void cp_wait0()  { asm volatile("cp.async.wait_group 0;\n" ::: "memory"); }

// Round-to-nearest tf32 conversion. Critical: raw f32 bits into mma would be
// truncation (biased ~ -0.5 ulp => ~1e-3 systematic error). rna keeps it ~2e-4.
DEVINL uint32_t f2tf32(float f) {
    uint32_t r;
    asm("cvt.rna.tf32.f32 %0, %1;\n" : "=r"(r) : "f"(f));
    return r;
}

DEVINL void mma_tf32(float* c, const uint32_t* a, const uint32_t* b) {
    asm volatile(
        "mma.sync.aligned.m16n8k8.row.col.f32.tf32.tf32.f32 "
        "{%0,%1,%2,%3}, {%4,%5,%6,%7}, {%8,%9}, {%0,%1,%2,%3};\n"
        : "+f"(c[0]), "+f"(c[1]), "+f"(c[2]), "+f"(c[3])
        : "r"(a[0]), "r"(a[1]), "r"(a[2]), "r"(a[3]), "r"(b[0]), "r"(b[1]));
}

// ======================= Stage 1: QKV projections =======================
// C[8192,1024] = X[8192,1024] @ W[1024,1024] + bias ; scattered to [B,H,S,hd]
constexpr int BM = 128, BN = 128, BK = 32;
constexpr int ASTR = 36;   // 36 mod 32 = 4  -> a-frag lane addr = 4*g + t (conflict-free)
constexpr int BSTR = 136;  // 136 mod 32 = 8 -> b-frag lane addr = 8*t + g (conflict-free)
constexpr int GEMM_SMEM_BYTES = (2 * BM * ASTR + 2 * BK * BSTR) * 4;  // 71680

__global__ __launch_bounds__(256) void qkv_kernel(
    const float* __restrict__ X,
    const float* __restrict__ Wq, const float* __restrict__ bq,
    const float* __restrict__ Wk, const float* __restrict__ bk,
    const float* __restrict__ Wv, const float* __restrict__ bv)
{
    extern __shared__ float sm[];
    float* As  = sm;
    float* Bsh = sm + 2 * BM * ASTR;

    const int z = blockIdx.z;
    const float* W   = (z == 0) ? Wq : (z == 1) ? Wk : Wv;
    const float* bia = (z == 0) ? bq : (z == 1) ? bk : bv;
    float* outp      = (z == 0) ? g_q : (z == 1) ? g_k : g_v;
    const float scl  = (z == 0) ? 0.125f : 1.0f;  // hd^-0.5 folded into Q

    const int bm = blockIdx.y * BM;
    const int bn = blockIdx.x * BN;
    const int tid = threadIdx.x;
    const int wid = tid >> 5, lane = tid & 31;
    const int wm = (wid >> 2) * 64, wn = (wid & 3) * 32;
    const int g = lane >> 2, t = lane & 3;

    float acc[4][4][4];
    #pragma unroll
    for (int mt = 0; mt < 4; ++mt)
        #pragma unroll
        for (int nt = 0; nt < 4; ++nt)
            #pragma unroll
            for (int i = 0; i < 4; ++i) acc[mt][nt][i] = 0.0f;

    auto load_stage = [&](int st, int k0) {
        float* A  = As  + st * BM * ASTR;
        float* Bm = Bsh + st * BK * BSTR;
        #pragma unroll
        for (int c = 0; c < 4; ++c) {   // A: 128x32 f32 = 1024 vec4
            int lin = tid + c * 256;
            int ar = lin >> 3, ak = (lin & 7) * 4;
            cp_async16(smem_u32(A + ar * ASTR + ak),
                       X + (long long)(bm + ar) * kD + k0 + ak);
        }
        #pragma unroll
        for (int c = 0; c < 4; ++c) {   // B: 32x128 f32
            int lin = tid + c * 256;
            int br = lin >> 5, bnc = (lin & 31) * 4;
            cp_async16(smem_u32(Bm + br * BSTR + bnc),
                       W + (long long)(k0 + br) * kD + bn + bnc);
        }
        cp_commit();
    };

    load_stage(0, 0);
    #pragma unroll 1
    for (int kk = 0; kk < kD; kk += BK) {
        cp_wait0();
        __syncthreads();
        if (kk + BK < kD) load_stage(((kk >> 5) + 1) & 1, kk + BK);

        const float* A  = As  + ((kk >> 5) & 1) * BM * ASTR;
        const float* Bm = Bsh + ((kk >> 5) & 1) * BK * BSTR;

        #pragma unroll
        for (int kt = 0; kt < 4; ++kt) {
            uint32_t af[4][4], bf[4][2];
            #pragma unroll
            for (int mt = 0; mt < 4; ++mt) {
                const float* ap = A + (wm + mt * 16) * ASTR + kt * 8 + t;
                af[mt][0] = f2tf32(ap[g * ASTR]);
                af[mt][1] = f2tf32(ap[(g + 8) * ASTR]);
                af[mt][2] = f2tf32(ap[g * ASTR + 4]);
                af[mt][3] = f2tf32(ap[(g + 8) * ASTR + 4]);
            }
            #pragma unroll
            for (int nt = 0; nt < 4; ++nt) {
                const float* bp = Bm + (kt * 8 + t) * BSTR + wn + nt * 8 + g;
                bf[nt][0] = f2tf32(bp[0]);
                bf[nt][1] = f2tf32(bp[4 * BSTR]);
            }
            #pragma unroll
            for (int mt = 0; mt < 4; ++mt)
                #pragma unroll
                for (int nt = 0; nt < 4; ++nt)
                    mma_tf32(acc[mt][nt], af[mt], bf[nt]);
        }
    }

    // Epilogue: + bias, * scale, scatter to [B, H, S, hd]
    #pragma unroll
    for (int mt = 0; mt < 4; ++mt) {
        #pragma unroll
        for (int nt = 0; nt < 4; ++nt) {
            const int col = bn + wn + nt * 8 + 2 * t;       // even
            const int hh = col >> 6, d0 = col & 63;
            const float b0 = bia[col], b1 = bia[col + 1];
            #pragma unroll
            for (int rr = 0; rr < 2; ++rr) {
                const int m = bm + wm + mt * 16 + g + rr * 8;
                const int bb = m >> 11, ss = m & 2047;
                float2 v;
                v.x = (acc[mt][nt][rr * 2 + 0] + b0) * scl;
                v.y = (acc[mt][nt][rr * 2 + 1] + b1) * scl;
                *(float2*)&outp[((long long)(bb * kH + hh) * kS + ss) * kHD + d0] = v;
            }
        }
    }
}

// ======================= Stage 2: flash attention =======================
// One CTA = (b, h, 64-row Q tile). 4 warps, each owns 16 Q rows.
// Streams 64-key tiles with online softmax; O accumulated in registers.
constexpr int KSTR = 68;  // 68 mod 32 = 4 -> S-mma B-frag reads conflict-free
constexpr int VSTR = 72;  // 72 mod 32 = 8 -> O-mma B-frag reads conflict-free
constexpr int PSTR = 68;  // P A-frag reads conflict-free
constexpr int ATTN_SMEM_BYTES = (64 * KSTR + 64 * VSTR + 64 * PSTR + 64) * 4;  // 53504

__global__ __launch_bounds__(128) void attn_kernel(
    const float* __restrict__ mask, float* __restrict__ out)
{
    extern __shared__ float sm[];
    float* Ks = sm;
    float* Vs = Ks + 64 * KSTR;
    float* Ps = Vs + 64 * VSTR;
    float* Ms = Ps + 64 * PSTR;

    const int bh = blockIdx.y;
    const int b = bh >> 4, h = bh & 15;
    const int q0 = blockIdx.x * 64;
    const int tid = threadIdx.x, wid = tid >> 5, lane = tid & 31;
    const int g = lane >> 2, t = lane & 3;

    const float* qptr = g_q + ((long long)bh * kS + q0) * kHD;
    const float* kptr = g_k + (long long)bh * kS * kHD;
    const float* vptr = g_v + (long long)bh * kS * kHD;

    // Stage Q (64x64) through smem once -> register-resident tf32 fragments.
    #pragma unroll
    for (int i = 0; i < 8; ++i) {
        int lin = tid + i * 128;
        int r = lin >> 4, c = (lin & 15) * 4;
        *(float4*)&Ks[r * KSTR + c] = *(const float4*)&qptr[r * kHD + c];
    }
    __syncthreads();
    uint32_t qf[8][4];
    {
        const int r = wid * 16 + g;
        #pragma unroll
        for (int kt = 0; kt < 8; ++kt) {
            qf[kt][0] = f2tf32(Ks[r * KSTR + kt * 8 + t]);
            qf[kt][1] = f2tf32(Ks[(r + 8) * KSTR + kt * 8 + t]);
            qf[kt][2] = f2tf32(Ks[r * KSTR + kt * 8 + t + 4]);
            qf[kt][3] = f2tf32(Ks[(r + 8) * KSTR + kt * 8 + t + 4]);
        }
    }

    float o[8][4];
    #pragma unroll
    for (int nv = 0; nv < 8; ++nv)
        #pragma unroll
        for (int i = 0; i < 4; ++i) o[nv][i] = 0.0f;
    float mrow[2] = {-1e30f, -1e30f};
    float lrow[2] = {0.0f, 0.0f};

    #pragma unroll 1
    for (int k0 = 0; k0 < kS; k0 += 64) {
        __syncthreads();  // prior iter done reading Ks/Vs (covers Q staging too)
        #pragma unroll
        for (int i = 0; i < 8; ++i) {
            int lin = tid + i * 128;
            int r = lin >> 4, c = (lin & 15) * 4;
            *(float4*)&Ks[r * KSTR + c] = *(const float4*)&kptr[(long long)(k0 + r) * kHD + c];
            *(float4*)&Vs[r * VSTR + c] = *(const float4*)&vptr[(long long)(k0 + r) * kHD + c];
        }
        if (tid < 16)
            *(float4*)&Ms[tid * 4] = *(const float4*)&mask[b * kS + k0 + tid * 4];
        __syncthreads();

        // ---- S = Q @ K^T  (warp: 16 q-rows x 64 keys) ----
        float sc[8][4];
        #pragma unroll
        for (int nt = 0; nt < 8; ++nt) {
            sc[nt][0] = sc[nt][1] = sc[nt][2] = sc[nt][3] = 0.0f;
            #pragma unroll
            for (int kt = 0; kt < 8; ++kt) {
                uint32_t bf[2];
                const float* kp = Ks + (nt * 8 + g) * KSTR + kt * 8 + t;
                bf[0] = f2tf32(kp[0]);
                bf[1] = f2tf32(kp[4]);
                mma_tf32(sc[nt], qf[kt], bf);
            }
        }

        // ---- + mask, online softmax ----
        #pragma unroll
        for (int nt = 0; nt < 8; ++nt) {
            const float m0 = Ms[nt * 8 + 2 * t], m1 = Ms[nt * 8 + 2 * t + 1];
            sc[nt][0] += m0; sc[nt][1] += m1;
            sc[nt][2] += m0; sc[nt][3] += m1;
        }
        float mx0 = -1e30f, mx1 = -1e30f;
        #pragma unroll
        for (int nt = 0; nt < 8; ++nt) {
            mx0 = fmaxf(mx0, fmaxf(sc[nt][0], sc[nt][1]));
            mx1 = fmaxf(mx1, fmaxf(sc[nt][2], sc[nt][3]));
        }
        #pragma unroll
        for (int s = 1; s < 4; s <<= 1) {
            mx0 = fmaxf(mx0, __shfl_xor_sync(0xffffffffu, mx0, s));
            mx1 = fmaxf(mx1, __shfl_xor_sync(0xffffffffu, mx1, s));
        }
        const float mn0 = fmaxf(mrow[0], mx0);
        const float mn1 = fmaxf(mrow[1], mx1);
        const float cr0 = __expf(mrow[0] - mn0);
        const float cr1 = __expf(mrow[1] - mn1);

        float ls0 = 0.0f, ls1 = 0.0f;
        {
            const int r = wid * 16 + g;
            #pragma unroll
            for (int nt = 0; nt < 8; ++nt) {
                float2 p01, p23;
                p01.x = __expf(sc[nt][0] - mn0);
                p01.y = __expf(sc[nt][1] - mn0);
                p23.x = __expf(sc[nt][2] - mn1);
                p23.y = __expf(sc[nt][3] - mn1);
                ls0 += p01.x + p01.y;
                ls1 += p23.x + p23.y;
                *(float2*)&Ps[r * PSTR + nt * 8 + 2 * t] = p01;
                *(float2*)&Ps[(r + 8) * PSTR + nt * 8 + 2 * t] = p23;
            }
        }
        #pragma unroll
        for (int s = 1; s < 4; s <<= 1) {
            ls0 += __shfl_xor_sync(0xffffffffu, ls0, s);
            ls1 += __shfl_xor_sync(0xffffffffu, ls1, s);
        }
        lrow[0] = lrow[0] * cr0 + ls0;
        lrow[1] = lrow[1] * cr1 + ls1;
        mrow[0] = mn0;
        mrow[1] = mn1;
        #pragma unroll
        for (int nv = 0; nv < 8; ++nv) {
            o[nv][0] *= cr0; o[nv][1] *= cr0;
            o[nv][2] *= cr1; o[nv][3] *= cr1;
        }
        __syncwarp();

        // ---- O += P @ V ----
        #pragma unroll
        for (int kt = 0; kt < 8; ++kt) {
            uint32_t pf[4];
            const int r = wid * 16 + g;
            pf[0] = f2tf32(Ps[r * PSTR + kt * 8 + t]);
            pf[1] = f2tf32(Ps[(r + 8) * PSTR + kt * 8 + t]);
            pf[2] = f2tf32(Ps[r * PSTR + kt * 8 + t + 4]);
            pf[3] = f2tf32(Ps[(r + 8) * PSTR + kt * 8 + t + 4]);
            #pragma unroll
            for (int nv = 0; nv < 8; ++nv) {
                uint32_t bf[2];
                const float* vp = Vs + (kt * 8 + t) * VSTR + nv * 8 + g;
                bf[0] = f2tf32(vp[0]);
                bf[1] = f2tf32(vp[4 * VSTR]);
                mma_tf32(o[nv], pf, bf);
            }
        }
    }

    // ---- epilogue: divide by row sums, write [B, S, D] ----
    const float inv0 = 1.0f / lrow[0];
    const float inv1 = 1.0f / lrow[1];
    const int srow = q0 + wid * 16 + g;
    #pragma unroll
    for (int nv = 0; nv < 8; ++nv) {
        const int d0 = h * 64 + nv * 8 + 2 * t;
        float2 v0, v1;
        v0.x = o[nv][0] * inv0; v0.y = o[nv][1] * inv0;
        v1.x = o[nv][2] * inv1; v1.y = o[nv][3] * inv1;
        *(float2*)&out[((long long)(b * kS + srow)) * kD + d0] = v0;
        *(float2*)&out[((long long)(b * kS + srow + 8)) * kD + d0] = v1;
    }
}

// ======================= launch =======================
extern "C" void kernel_launch(void* const* d_in, const int* in_sizes, int n_in,
                              void* d_out, int out_size)
{
    (void)in_sizes; (void)n_in; (void)out_size;
    const float* X    = (const float*)d_in[0];
    const float* mask = (const float*)d_in[1];
    const float* Wq   = (const float*)d_in[2];
    const float* bq   = (const float*)d_in[3];
    const float* Wk   = (const float*)d_in[4];
    const float* bk   = (const float*)d_in[5];
    const float* Wv   = (const float*)d_in[6];
    const float* bv   = (const float*)d_in[7];
    float* out = (float*)d_out;

    // Idempotent, called every launch (no static guards allowed).
    cudaFuncSetAttribute(qkv_kernel, cudaFuncAttributeMaxDynamicSharedMemorySize,
                         GEMM_SMEM_BYTES);
    cudaFuncSetAttribute(attn_kernel, cudaFuncAttributeMaxDynamicSharedMemorySize,
                         ATTN_SMEM_BYTES);

    qkv_kernel<<<dim3(kD / BN, kM / BM, 3), 256, GEMM_SMEM_BYTES>>>(
        X, Wq, bq, Wk, bk, Wv, bv);
    attn_kernel<<<dim3(kS / 64, kB * kH), 128, ATTN_SMEM_BYTES>>>(mask, out);
}

// round 2
// speedup vs baseline: 1.3446x; 1.3446x over previous
#include <cuda_runtime.h>
#include <cstdint>

#define DEVINL __device__ __forceinline__

constexpr int kB = 4, kS = 2048, kD = 1024, kH = 16, kHD = 64;
constexpr int kM = kB * kS;  // 8192 rows for QKV GEMM

// Scratch: Q/K/V in [B, H, S, hd] layout (head-major for attention).
__device__ float g_q[(long long)kB * kH * kS * kHD];
__device__ float g_k[(long long)kB * kH * kS * kHD];
__device__ float g_v[(long long)kB * kH * kS * kHD];

DEVINL uint32_t smem_u32(const void* p) {
    return (uint32_t)__cvta_generic_to_shared(p);
}
DEVINL void cp_async16(uint32_t dst, const void* src) {
    asm volatile("cp.async.cg.shared.global [%0], [%1], 16;\n" ::"r"(dst), "l"(src));
}
DEVINL void cp_commit() { asm volatile("cp.async.commit_group;\n" ::: "memory"); }
DEVINL void cp_wait0()  { asm volatile("cp.async.wait_group 0;\n" ::: "memory"); }

// Round-to-nearest tf32 conversion (rna avoids the -0.5ulp truncation bias).
DEVINL uint32_t f2tf32(float f) {
    uint32_t r;
    asm("cvt.rna.tf32.f32 %0, %1;\n" : "=r"(r) : "f"(f));
    return r;
}

DEVINL void mma_tf32(float* c, const uint32_t* a, const uint32_t* b) {
    asm volatile(
        "mma.sync.aligned.m16n8k8.row.col.f32.tf32.tf32.f32 "
        "{%0,%1,%2,%3}, {%4,%5,%6,%7}, {%8,%9}, {%0,%1,%2,%3};\n"
        : "+f"(c[0]), "+f"(c[1]), "+f"(c[2]), "+f"(c[3])
        : "r"(a[0]), "r"(a[1]), "r"(a[2]), "r"(a[3]), "r"(b[0]), "r"(b[1]));
}

// ======================= Stage 1: QKV projections =======================
// C[8192,1024] = X[8192,1024] @ W[1024,1024] + bias ; scattered to [B,H,S,hd]
constexpr int BM = 128, BN = 128, BK = 32;
constexpr int ASTR = 36;   // 36 mod 32 = 4  -> conflict-free a-frag reads
constexpr int BSTR = 136;  // 136 mod 32 = 8 -> conflict-free b-frag reads
constexpr int GEMM_SMEM_BYTES = (2 * BM * ASTR + 2 * BK * BSTR) * 4;  // 71680

__global__ __launch_bounds__(256) void qkv_kernel(
    const float* __restrict__ X,
    const float* __restrict__ Wq, const float* __restrict__ bq,
    const float* __restrict__ Wk, const float* __restrict__ bk,
    const float* __restrict__ Wv, const float* __restrict__ bv)
{
    extern __shared__ float sm[];
    float* As  = sm;
    float* Bsh = sm + 2 * BM * ASTR;

    const int z = blockIdx.z;
    const float* W   = (z == 0) ? Wq : (z == 1) ? Wk : Wv;
    const float* bia = (z == 0) ? bq : (z == 1) ? bk : bv;
    float* outp      = (z == 0) ? g_q : (z == 1) ? g_k : g_v;
    const float scl  = (z == 0) ? 0.125f : 1.0f;  // hd^-0.5 folded into Q

    const int bm = blockIdx.y * BM;
    const int bn = blockIdx.x * BN;
    const int tid = threadIdx.x;
    const int wid = tid >> 5, lane = tid & 31;
    const int wm = (wid >> 2) * 64, wn = (wid & 3) * 32;
    const int g = lane >> 2, t = lane & 3;

    float acc[4][4][4];
    #pragma unroll
    for (int mt = 0; mt < 4; ++mt)
        #pragma unroll
        for (int nt = 0; nt < 4; ++nt)
            #pragma unroll
            for (int i = 0; i < 4; ++i) acc[mt][nt][i] = 0.0f;

    auto load_stage = [&](int st, int k0) {
        float* A  = As  + st * BM * ASTR;
        float* Bm = Bsh + st * BK * BSTR;
        #pragma unroll
        for (int c = 0; c < 4; ++c) {
            int lin = tid + c * 256;
            int ar = lin >> 3, ak = (lin & 7) * 4;
            cp_async16(smem_u32(A + ar * ASTR + ak),
                       X + (long long)(bm + ar) * kD + k0 + ak);
        }
        #pragma unroll
        for (int c = 0; c < 4; ++c) {
            int lin = tid + c * 256;
            int br = lin >> 5, bnc = (lin & 31) * 4;
            cp_async16(smem_u32(Bm + br * BSTR + bnc),
                       W + (long long)(k0 + br) * kD + bn + bnc);
        }
        cp_commit();
    };

    load_stage(0, 0);
    #pragma unroll 1
    for (int kk = 0; kk < kD; kk += BK) {
        cp_wait0();
        __syncthreads();
        if (kk + BK < kD) load_stage(((kk >> 5) + 1) & 1, kk + BK);

        const float* A  = As  + ((kk >> 5) & 1) * BM * ASTR;
        const float* Bm = Bsh + ((kk >> 5) & 1) * BK * BSTR;

        #pragma unroll
        for (int kt = 0; kt < 4; ++kt) {
            uint32_t af[4][4], bf[4][2];
            #pragma unroll
            for (int mt = 0; mt < 4; ++mt) {
                const float* ap = A + (wm + mt * 16) * ASTR + kt * 8 + t;
                af[mt][0] = f2tf32(ap[g * ASTR]);
                af[mt][1] = f2tf32(ap[(g + 8) * ASTR]);
                af[mt][2] = f2tf32(ap[g * ASTR + 4]);
                af[mt][3] = f2tf32(ap[(g + 8) * ASTR + 4]);
            }
            #pragma unroll
            for (int nt = 0; nt < 4; ++nt) {
                const float* bp = Bm + (kt * 8 + t) * BSTR + wn + nt * 8 + g;
                bf[nt][0] = f2tf32(bp[0]);
                bf[nt][1] = f2tf32(bp[4 * BSTR]);
            }
            #pragma unroll
            for (int mt = 0; mt < 4; ++mt)
                #pragma unroll
                for (int nt = 0; nt < 4; ++nt)
                    mma_tf32(acc[mt][nt], af[mt], bf[nt]);
        }
    }

    #pragma unroll
    for (int mt = 0; mt < 4; ++mt) {
        #pragma unroll
        for (int nt = 0; nt < 4; ++nt) {
            const int col = bn + wn + nt * 8 + 2 * t;       // even
            const int hh = col >> 6, d0 = col & 63;
            const float b0 = bia[col], b1 = bia[col + 1];
            #pragma unroll
            for (int rr = 0; rr < 2; ++rr) {
                const int m = bm + wm + mt * 16 + g + rr * 8;
                const int bb = m >> 11, ss = m & 2047;
                float2 v;
                v.x = (acc[mt][nt][rr * 2 + 0] + b0) * scl;
                v.y = (acc[mt][nt][rr * 2 + 1] + b1) * scl;
                *(float2*)&outp[((long long)(bb * kH + hh) * kS + ss) * kHD + d0] = v;
            }
        }
    }
}

// ======================= Stage 2: flash attention =======================
// CTA = (b, h, 128-row Q tile). 4 warps x 32 rows (2 m-tiles each).
// K/V/P live in smem as PRE-CONVERTED tf32 bit patterns; b-fragments are
// shared across both m-tiles (K) and 16 mmas (V) to cut LDS-per-mma ~2.5x.
constexpr int KSTR = 68;  // mod 32 = 4 -> conflict-free K b-frag & Q a-frag reads
constexpr int VSTR = 72;  // mod 32 = 8 -> conflict-free V b-frag reads
constexpr int PSTR = 68;  // conflict-free P a-frag reads
constexpr int ATTN_SMEM_BYTES = (64 * KSTR + 64 * VSTR + 128 * PSTR + 64) * 4;  // 70912

__global__ __launch_bounds__(128) void attn_kernel(
    const float* __restrict__ mask, float* __restrict__ out)
{
    extern __shared__ float sm[];
    float* Ks = sm;                      // 64 x 68 (tf32 bits)
    float* Vs = Ks + 64 * KSTR;          // 64 x 72 (tf32 bits)
    float* Ps = Vs + 64 * VSTR;          // 128 x 68 (tf32 bits)
    float* Ms = Ps + 128 * PSTR;         // 64

    const int bh = blockIdx.y;
    const int b = bh >> 4, h = bh & 15;
    const int q0 = blockIdx.x * 128;
    const int tid = threadIdx.x, wid = tid >> 5, lane = tid & 31;
    const int g = lane >> 2, t = lane & 3;

    const float* qptr = g_q + ((long long)bh * kS + q0) * kHD;
    const float* kptr = g_k + (long long)bh * kS * kHD;
    const float* vptr = g_v + (long long)bh * kS * kHD;

    // ---- stage Q (two 64-row halves through Ks) -> register tf32 fragments
    uint32_t qf[2][8][4];
    #pragma unroll 1
    for (int half = 0; half < 2; ++half) {
        __syncthreads();
        #pragma unroll
        for (int i = 0; i < 8; ++i) {
            int lin = tid + i * 128;
            int r = lin >> 4, c = (lin & 15) * 4;
            float4 qv = *(const float4*)&qptr[(long long)(half * 64 + r) * kHD + c];
            float4 qt;
            qt.x = __uint_as_float(f2tf32(qv.x));
            qt.y = __uint_as_float(f2tf32(qv.y));
            qt.z = __uint_as_float(f2tf32(qv.z));
            qt.w = __uint_as_float(f2tf32(qv.w));
            *(float4*)&Ks[r * KSTR + c] = qt;
        }
        __syncthreads();
        if ((wid >> 1) == half) {
            const int lr = (wid & 1) * 32 + g;
            #pragma unroll
            for (int mt = 0; mt < 2; ++mt)
                #pragma unroll
                for (int kt = 0; kt < 8; ++kt) {
                    const float* qp = Ks + (lr + mt * 16) * KSTR + kt * 8 + t;
                    qf[mt][kt][0] = __float_as_uint(qp[0]);
                    qf[mt][kt][1] = __float_as_uint(qp[8 * KSTR]);
                    qf[mt][kt][2] = __float_as_uint(qp[4]);
                    qf[mt][kt][3] = __float_as_uint(qp[8 * KSTR + 4]);
                }
        }
    }

    float o[2][8][4];
    #pragma unroll
    for (int mt = 0; mt < 2; ++mt)
        #pragma unroll
        for (int nv = 0; nv < 8; ++nv)
            #pragma unroll
            for (int i = 0; i < 4; ++i) o[mt][nv][i] = 0.0f;
    float mrow[2][2] = {{-1e30f, -1e30f}, {-1e30f, -1e30f}};
    float lrow[2][2] = {{0.0f, 0.0f}, {0.0f, 0.0f}};

    #pragma unroll 1
    for (int k0 = 0; k0 < kS; k0 += 64) {
        __syncthreads();  // prior iter done reading Ks/Vs
        #pragma unroll
        for (int i = 0; i < 8; ++i) {
            int lin = tid + i * 128;
            int r = lin >> 4, c = (lin & 15) * 4;
            float4 kv = *(const float4*)&kptr[(long long)(k0 + r) * kHD + c];
            float4 vv = *(const float4*)&vptr[(long long)(k0 + r) * kHD + c];
            float4 ktt, vtt;
            ktt.x = __uint_as_float(f2tf32(kv.x));
            ktt.y = __uint_as_float(f2tf32(kv.y));
            ktt.z = __uint_as_float(f2tf32(kv.z));
            ktt.w = __uint_as_float(f2tf32(kv.w));
            vtt.x = __uint_as_float(f2tf32(vv.x));
            vtt.y = __uint_as_float(f2tf32(vv.y));
            vtt.z = __uint_as_float(f2tf32(vv.z));
            vtt.w = __uint_as_float(f2tf32(vv.w));
            *(float4*)&Ks[r * KSTR + c] = ktt;
            *(float4*)&Vs[r * VSTR + c] = vtt;
        }
        if (tid < 16)
            *(float4*)&Ms[tid * 4] = *(const float4*)&mask[b * kS + k0 + tid * 4];
        __syncthreads();

        // ---- S = Q @ K^T : both m-tiles share each K b-fragment ----
        float sc[2][8][4];
        #pragma unroll
        for (int mt = 0; mt < 2; ++mt)
            #pragma unroll
            for (int nt = 0; nt < 8; ++nt)
                #pragma unroll
                for (int i = 0; i < 4; ++i) sc[mt][nt][i] = 0.0f;
        #pragma unroll
        for (int nt = 0; nt < 8; ++nt) {
            #pragma unroll
            for (int kt = 0; kt < 8; ++kt) {
                uint32_t bf[2];
                const float* kp = Ks + (nt * 8 + g) * KSTR + kt * 8 + t;
                bf[0] = __float_as_uint(kp[0]);
                bf[1] = __float_as_uint(kp[4]);
                mma_tf32(sc[0][nt], qf[0][kt], bf);
                mma_tf32(sc[1][nt], qf[1][kt], bf);
            }
        }

        // ---- mask + online softmax (per m-tile); P -> smem as tf32 ----
        #pragma unroll
        for (int mt = 0; mt < 2; ++mt) {
            #pragma unroll
            for (int nt = 0; nt < 8; ++nt) {
                const float m0 = Ms[nt * 8 + 2 * t], m1 = Ms[nt * 8 + 2 * t + 1];
                sc[mt][nt][0] += m0; sc[mt][nt][1] += m1;
                sc[mt][nt][2] += m0; sc[mt][nt][3] += m1;
            }
            float mx0 = -1e30f, mx1 = -1e30f;
            #pragma unroll
            for (int nt = 0; nt < 8; ++nt) {
                mx0 = fmaxf(mx0, fmaxf(sc[mt][nt][0], sc[mt][nt][1]));
                mx1 = fmaxf(mx1, fmaxf(sc[mt][nt][2], sc[mt][nt][3]));
            }
            #pragma unroll
            for (int s = 1; s < 4; s <<= 1) {
                mx0 = fmaxf(mx0, __shfl_xor_sync(0xffffffffu, mx0, s));
                mx1 = fmaxf(mx1, __shfl_xor_sync(0xffffffffu, mx1, s));
            }
            const float mn0 = fmaxf(mrow[mt][0], mx0);
            const float mn1 = fmaxf(mrow[mt][1], mx1);
            const float cr0 = __expf(mrow[mt][0] - mn0);
            const float cr1 = __expf(mrow[mt][1] - mn1);

            float ls0 = 0.0f, ls1 = 0.0f;
            const int r = wid * 32 + mt * 16 + g;
            #pragma unroll
            for (int nt = 0; nt < 8; ++nt) {
                float p0 = __expf(sc[mt][nt][0] - mn0);
                float p1 = __expf(sc[mt][nt][1] - mn0);
                float p2 = __expf(sc[mt][nt][2] - mn1);
                float p3 = __expf(sc[mt][nt][3] - mn1);
                ls0 += p0 + p1;
                ls1 += p2 + p3;
                float2 w0, w1;
                w0.x = __uint_as_float(f2tf32(p0));
                w0.y = __uint_as_float(f2tf32(p1));
                w1.x = __uint_as_float(f2tf32(p2));
                w1.y = __uint_as_float(f2tf32(p3));
                *(float2*)&Ps[r * PSTR + nt * 8 + 2 * t] = w0;
                *(float2*)&Ps[(r + 8) * PSTR + nt * 8 + 2 * t] = w1;
            }
            #pragma unroll
            for (int s = 1; s < 4; s <<= 1) {
                ls0 += __shfl_xor_sync(0xffffffffu, ls0, s);
                ls1 += __shfl_xor_sync(0xffffffffu, ls1, s);
            }
            lrow[mt][0] = lrow[mt][0] * cr0 + ls0;
            lrow[mt][1] = lrow[mt][1] * cr1 + ls1;
            mrow[mt][0] = mn0;
            mrow[mt][1] = mn1;
            #pragma unroll
            for (int nv = 0; nv < 8; ++nv) {
                o[mt][nv][0] *= cr0; o[mt][nv][1] *= cr0;
                o[mt][nv][2] *= cr1; o[mt][nv][3] *= cr1;
            }
        }
        __syncwarp();

        // ---- O += P @ V : V b-frags shared across both m-tiles ----
        #pragma unroll
        for (int kt = 0; kt < 8; ++kt) {
            uint32_t bv[8][2];
            #pragma unroll
            for (int nv = 0; nv < 8; ++nv) {
                const float* vp = Vs + (kt * 8 + t) * VSTR + nv * 8 + g;
                bv[nv][0] = __float_as_uint(vp[0]);
                bv[nv][1] = __float_as_uint(vp[4 * VSTR]);
            }
            #pragma unroll
            for (int mt = 0; mt < 2; ++mt) {
                const int r = wid * 32 + mt * 16 + g;
                uint32_t pf[4];
                const float* pp = Ps + r * PSTR + kt * 8 + t;
                pf[0] = __float_as_uint(pp[0]);
                pf[1] = __float_as_uint(pp[8 * PSTR]);
                pf[2] = __float_as_uint(pp[4]);
                pf[3] = __float_as_uint(pp[8 * PSTR + 4]);
                #pragma unroll
                for (int nv = 0; nv < 8; ++nv)
                    mma_tf32(o[mt][nv], pf, bv[nv]);
            }
        }
    }

    // ---- epilogue: divide by row sums, write [B, S, D] ----
    #pragma unroll
    for (int mt = 0; mt < 2; ++mt) {
        const float inv0 = 1.0f / lrow[mt][0];
        const float inv1 = 1.0f / lrow[mt][1];
        const int srow = q0 + wid * 32 + mt * 16 + g;
        #pragma unroll
        for (int nv = 0; nv < 8; ++nv) {
            const int d0 = h * 64 + nv * 8 + 2 * t;
            float2 v0, v1;
            v0.x = o[mt][nv][0] * inv0; v0.y = o[mt][nv][1] * inv0;
            v1.x = o[mt][nv][2] * inv1; v1.y = o[mt][nv][3] * inv1;
            *(float2*)&out[((long long)(b * kS + srow)) * kD + d0] = v0;
            *(float2*)&out[((long long)(b * kS + srow + 8)) * kD + d0] = v1;
        }
    }
}

// ======================= launch =======================
extern "C" void kernel_launch(void* const* d_in, const int* in_sizes, int n_in,
                              void* d_out, int out_size)
{
    (void)in_sizes; (void)n_in; (void)out_size;
    const float* X    = (const float*)d_in[0];
    const float* mask = (const float*)d_in[1];
    const float* Wq   = (const float*)d_in[2];
    const float* bq   = (const float*)d_in[3];
    const float* Wk   = (const float*)d_in[4];
    const float* bk   = (const float*)d_in[5];
    const float* Wv   = (const float*)d_in[6];
    const float* bv   = (const float*)d_in[7];
    float* out = (float*)d_out;

    cudaFuncSetAttribute(qkv_kernel, cudaFuncAttributeMaxDynamicSharedMemorySize,
                         GEMM_SMEM_BYTES);
    cudaFuncSetAttribute(attn_kernel, cudaFuncAttributeMaxDynamicSharedMemorySize,
                         ATTN_SMEM_BYTES);

    qkv_kernel<<<dim3(kD / BN, kM / BM, 3), 256, GEMM_SMEM_BYTES>>>(
        X, Wq, bq, Wk, bk, Wv, bv);
    attn_kernel<<<dim3(kS / 128, kB * kH), 128, ATTN_SMEM_BYTES>>>(mask, out);
}

// round 3
// speedup vs baseline: 1.4287x; 1.0626x over previous
#include <cuda_runtime.h>
#include <cstdint>

#define DEVINL __device__ __forceinline__

constexpr int kB = 4, kS = 2048, kD = 1024, kH = 16, kHD = 64;
constexpr int kM = kB * kS;  // 8192 rows for QKV GEMM

// Scratch (values stored PRE-ROUNDED to tf32 bit patterns):
// g_q, g_k : [B, H, S, hd]   g_v : [B, H, hd, S] (transposed for ldmatrix PV)
__device__ float g_q[(long long)kB * kH * kS * kHD];
__device__ float g_k[(long long)kB * kH * kS * kHD];
__device__ float g_v[(long long)kB * kH * kS * kHD];

DEVINL uint32_t smem_u32(const void* p) {
    return (uint32_t)__cvta_generic_to_shared(p);
}
DEVINL void cp_async16(uint32_t dst, const void* src) {
    asm volatile("cp.async.cg.shared.global [%0], [%1], 16;\n" ::"r"(dst), "l"(src));
}
DEVINL void cp_commit() { asm volatile("cp.async.commit_group;\n" ::: "memory"); }
template <int N> DEVINL void cp_wait() {
    asm volatile("cp.async.wait_group %0;\n" ::"n"(N) : "memory");
}

// Round-to-nearest tf32 (rna avoids the -0.5ulp truncation bias).
DEVINL uint32_t f2tf32(float f) {
    uint32_t r;
    asm("cvt.rna.tf32.f32 %0, %1;\n" : "=r"(r) : "f"(f));
    return r;
}

DEVINL void mma_tf32(float* c, const uint32_t* a, const uint32_t* b) {
    asm volatile(
        "mma.sync.aligned.m16n8k8.row.col.f32.tf32.tf32.f32 "
        "{%0,%1,%2,%3}, {%4,%5,%6,%7}, {%8,%9}, {%0,%1,%2,%3};\n"
        : "+f"(c[0]), "+f"(c[1]), "+f"(c[2]), "+f"(c[3])
        : "r"(a[0]), "r"(a[1]), "r"(a[2]), "r"(a[3]), "r"(b[0]), "r"(b[1]));
}

DEVINL void ldsm4(uint32_t* r, uint32_t addr) {
    asm volatile(
        "ldmatrix.sync.aligned.m8n8.x4.shared.b16 {%0,%1,%2,%3}, [%4];\n"
        : "=r"(r[0]), "=r"(r[1]), "=r"(r[2]), "=r"(r[3]) : "r"(addr));
}

// ======================= Stage 1: QKV projections =======================
constexpr int BM = 128, BN = 128, BK = 32;
constexpr int ASTR = 36;
constexpr int BSTR = 136;
constexpr int GEMM_SMEM_BYTES = (2 * BM * ASTR + 2 * BK * BSTR) * 4;  // 71680

__global__ __launch_bounds__(256) void qkv_kernel(
    const float* __restrict__ X,
    const float* __restrict__ Wq, const float* __restrict__ bq,
    const float* __restrict__ Wk, const float* __restrict__ bk,
    const float* __restrict__ Wv, const float* __restrict__ bv)
{
    extern __shared__ float sm[];
    float* As  = sm;
    float* Bsh = sm + 2 * BM * ASTR;

    const int z = blockIdx.z;
    const float* W   = (z == 0) ? Wq : (z == 1) ? Wk : Wv;
    const float* bia = (z == 0) ? bq : (z == 1) ? bk : bv;
    float* outp      = (z == 0) ? g_q : (z == 1) ? g_k : g_v;
    const float scl  = (z == 0) ? 0.125f : 1.0f;  // hd^-0.5 folded into Q

    const int bm = blockIdx.y * BM;
    const int bn = blockIdx.x * BN;
    const int tid = threadIdx.x;
    const int wid = tid >> 5, lane = tid & 31;
    const int wm = (wid >> 2) * 64, wn = (wid & 3) * 32;
    const int g = lane >> 2, t = lane & 3;

    float acc[4][4][4];
    #pragma unroll
    for (int mt = 0; mt < 4; ++mt)
        #pragma unroll
        for (int nt = 0; nt < 4; ++nt)
            #pragma unroll
            for (int i = 0; i < 4; ++i) acc[mt][nt][i] = 0.0f;

    auto load_stage = [&](int st, int k0) {
        float* A  = As  + st * BM * ASTR;
        float* Bm = Bsh + st * BK * BSTR;
        #pragma unroll
        for (int c = 0; c < 4; ++c) {
            int lin = tid + c * 256;
            int ar = lin >> 3, ak = (lin & 7) * 4;
            cp_async16(smem_u32(A + ar * ASTR + ak),
                       X + (long long)(bm + ar) * kD + k0 + ak);
        }
        #pragma unroll
        for (int c = 0; c < 4; ++c) {
            int lin = tid + c * 256;
            int br = lin >> 5, bnc = (lin & 31) * 4;
            cp_async16(smem_u32(Bm + br * BSTR + bnc),
                       W + (long long)(k0 + br) * kD + bn + bnc);
        }
        cp_commit();
    };

    load_stage(0, 0);
    #pragma unroll 1
    for (int kk = 0; kk < kD; kk += BK) {
        cp_wait<0>();
        __syncthreads();
        if (kk + BK < kD) load_stage(((kk >> 5) + 1) & 1, kk + BK);

        const float* A  = As  + ((kk >> 5) & 1) * BM * ASTR;
        const float* Bm = Bsh + ((kk >> 5) & 1) * BK * BSTR;

        #pragma unroll
        for (int kt = 0; kt < 4; ++kt) {
            uint32_t af[4][4], bf[4][2];
            #pragma unroll
            for (int mt = 0; mt < 4; ++mt) {
                const float* ap = A + (wm + mt * 16) * ASTR + kt * 8 + t;
                af[mt][0] = f2tf32(ap[g * ASTR]);
                af[mt][1] = f2tf32(ap[(g + 8) * ASTR]);
                af[mt][2] = f2tf32(ap[g * ASTR + 4]);
                af[mt][3] = f2tf32(ap[(g + 8) * ASTR + 4]);
            }
            #pragma unroll
            for (int nt = 0; nt < 4; ++nt) {
                const float* bp = Bm + (kt * 8 + t) * BSTR + wn + nt * 8 + g;
                bf[nt][0] = f2tf32(bp[0]);
                bf[nt][1] = f2tf32(bp[4 * BSTR]);
            }
            #pragma unroll
            for (int mt = 0; mt < 4; ++mt)
                #pragma unroll
                for (int nt = 0; nt < 4; ++nt)
                    mma_tf32(acc[mt][nt], af[mt], bf[nt]);
        }
    }

    // Epilogue: + bias, * scale, round to tf32, scatter.
    #pragma unroll
    for (int mt = 0; mt < 4; ++mt) {
        #pragma unroll
        for (int nt = 0; nt < 4; ++nt) {
            const int col = bn + wn + nt * 8 + 2 * t;  // even
            const int hh = col >> 6, d0 = col & 63;
            const float b0 = bia[col], b1 = bia[col + 1];
            #pragma unroll
            for (int rr = 0; rr < 2; ++rr) {
                const int m = bm + wm + mt * 16 + g + rr * 8;
                const int bb = m >> 11, ss = m & 2047;
                const float x0 = __uint_as_float(f2tf32((acc[mt][nt][rr * 2 + 0] + b0) * scl));
                const float x1 = __uint_as_float(f2tf32((acc[mt][nt][rr * 2 + 1] + b1) * scl));
                if (z < 2) {
                    float2 v; v.x = x0; v.y = x1;
                    *(float2*)&outp[((long long)(bb * kH + hh) * kS + ss) * kHD + d0] = v;
                } else {  // V transposed: [b,h][d][s]
                    const long long base = ((long long)(bb * kH + hh) * kHD + d0) * kS + ss;
                    outp[base] = x0;
                    outp[base + kS] = x1;
                }
            }
        }
    }
}

// ======================= Stage 2: flash attention =======================
// CTA = (b,h, 128-row Q tile), 4 warps x 32 rows. cp.async 2-stage K/V/mask
// pipeline (values pre-rounded tf32 => no cvt, pure LDGSTS). All mainloop
// fragments via ldmatrix.x4.
constexpr int KSTR = 68;   // stride mod 32 = 4 -> conflict-free LDSM tiles
constexpr int VSTR = 68;
constexpr int PSTR = 68;
constexpr int ATTN_SMEM_BYTES =
    (2 * 64 * KSTR + 2 * 64 * VSTR + 128 * PSTR + 128) * 4;  // 104960

__global__ __launch_bounds__(128) void attn_kernel(
    const float* __restrict__ mask, float* __restrict__ out)
{
    extern __shared__ float sm[];
    float* Kbuf = sm;                       // 2 x 64 x KSTR
    float* Vbuf = Kbuf + 2 * 64 * KSTR;     // 2 x 64 x VSTR (transposed: [d][s])
    float* Ps   = Vbuf + 2 * 64 * VSTR;     // 128 x PSTR
    float* Msk  = Ps + 128 * PSTR;          // 2 x 64

    const int bh = blockIdx.y;
    const int b = bh >> 4, h = bh & 15;
    const int q0 = blockIdx.x * 128;
    const int tid = threadIdx.x, wid = tid >> 5, lane = tid & 31;
    const int g = lane >> 2, t = lane & 3;
    const int lrow = lane & 7;
    const int lt8 = (lane >> 3) & 1, lt16 = (lane >> 4) & 1;

    const float* qptr = g_q + ((long long)bh * kS + q0) * kHD;
    const float* kptr = g_k + (long long)bh * kS * kHD;
    const float* vptr = g_v + (long long)bh * kHD * kS;  // [d][s]

    // LDSM per-lane base offsets (in floats)
    const int koff = lrow * KSTR + lt8 * 4 + lt16 * 8;            // K: x4 covers kt,kt+1
    const int voff = (lrow + lt16 * 8) * VSTR + lt8 * 4;          // V: x4 covers nv,nv+1
    const int poff = (wid * 32 + lrow + lt8 * 8) * PSTR + lt16 * 4;  // P a-frag

    // ---- Q fragments (pre-rounded) staged through Kbuf[0] ----
    uint32_t qf[2][8][4];
    #pragma unroll 1
    for (int half = 0; half < 2; ++half) {
        if (half) __syncthreads();
        #pragma unroll
        for (int i = 0; i < 8; ++i) {
            int lin = tid + i * 128;
            int r = lin >> 4, c = (lin & 15) * 4;
            *(float4*)&Kbuf[r * KSTR + c] =
                *(const float4*)&qptr[(long long)(half * 64 + r) * kHD + c];
        }
        __syncthreads();
        if ((wid >> 1) == half) {
            const int lr = (wid & 1) * 32 + g;
            #pragma unroll
            for (int mt = 0; mt < 2; ++mt)
                #pragma unroll
                for (int kt = 0; kt < 8; ++kt) {
                    const float* qp = Kbuf + (lr + mt * 16) * KSTR + kt * 8 + t;
                    qf[mt][kt][0] = __float_as_uint(qp[0]);
                    qf[mt][kt][1] = __float_as_uint(qp[8 * KSTR]);
                    qf[mt][kt][2] = __float_as_uint(qp[4]);
                    qf[mt][kt][3] = __float_as_uint(qp[8 * KSTR + 4]);
                }
        }
    }
    __syncthreads();

    auto prefetch = [&](int st, int k0) {
        float* Kd = Kbuf + st * 64 * KSTR;
        float* Vd = Vbuf + st * 64 * VSTR;
        #pragma unroll
        for (int i = 0; i < 8; ++i) {
            int ch = tid + i * 128;              // 0..1023
            int r = ch >> 4, c4 = (ch & 15) * 4;
            cp_async16(smem_u32(Kd + r * KSTR + c4),
                       kptr + (long long)(k0 + r) * kHD + c4);
            cp_async16(smem_u32(Vd + r * VSTR + c4),
                       vptr + (long long)r * kS + k0 + c4);
        }
        if (tid < 16)
            cp_async16(smem_u32(Msk + st * 64 + tid * 4),
                       mask + b * kS + k0 + tid * 4);
        cp_commit();
    };

    float o[2][8][4];
    #pragma unroll
    for (int mt = 0; mt < 2; ++mt)
        #pragma unroll
        for (int nv = 0; nv < 8; ++nv)
            #pragma unroll
            for (int i = 0; i < 4; ++i) o[mt][nv][i] = 0.0f;
    float mrow[2][2] = {{-1e30f, -1e30f}, {-1e30f, -1e30f}};
    float lrow2[2][2] = {{0.0f, 0.0f}, {0.0f, 0.0f}};

    prefetch(0, 0);

    #pragma unroll 1
    for (int it = 0; it < kS / 64; ++it) {
        const int st = it & 1;
        if (it + 1 < kS / 64) {
            prefetch(st ^ 1, (it + 1) * 64);
            cp_wait<1>();
        } else {
            cp_wait<0>();
        }
        __syncthreads();

        const float* Ks = Kbuf + st * 64 * KSTR;
        const float* Vs = Vbuf + st * 64 * VSTR;
        const float* Ms = Msk + st * 64;
        const uint32_t ks_base = smem_u32(Ks + koff);
        const uint32_t vs_base = smem_u32(Vs + voff);
        const uint32_t ps_base = smem_u32(Ps) + poff * 4;

        // ---- per m-tile: S = Q@K^T, mask, online softmax, P -> smem ----
        #pragma unroll
        for (int mt = 0; mt < 2; ++mt) {
            float sc[8][4];
            #pragma unroll
            for (int nt = 0; nt < 8; ++nt) {
                sc[nt][0] = sc[nt][1] = sc[nt][2] = sc[nt][3] = 0.0f;
                #pragma unroll
                for (int kt2 = 0; kt2 < 4; ++kt2) {
                    uint32_t bk[4];
                    ldsm4(bk, ks_base + (nt * 8 * KSTR + kt2 * 16) * 4);
                    mma_tf32(sc[nt], qf[mt][2 * kt2], bk);
                    mma_tf32(sc[nt], qf[mt][2 * kt2 + 1], bk + 2);
                }
            }
            #pragma unroll
            for (int nt = 0; nt < 8; ++nt) {
                const float m0 = Ms[nt * 8 + 2 * t], m1 = Ms[nt * 8 + 2 * t + 1];
                sc[nt][0] += m0; sc[nt][1] += m1;
                sc[nt][2] += m0; sc[nt][3] += m1;
            }
            float mx0 = -1e30f, mx1 = -1e30f;
            #pragma unroll
            for (int nt = 0; nt < 8; ++nt) {
                mx0 = fmaxf(mx0, fmaxf(sc[nt][0], sc[nt][1]));
                mx1 = fmaxf(mx1, fmaxf(sc[nt][2], sc[nt][3]));
            }
            #pragma unroll
            for (int s = 1; s < 4; s <<= 1) {
                mx0 = fmaxf(mx0, __shfl_xor_sync(0xffffffffu, mx0, s));
                mx1 = fmaxf(mx1, __shfl_xor_sync(0xffffffffu, mx1, s));
            }
            const float mn0 = fmaxf(mrow[mt][0], mx0);
            const float mn1 = fmaxf(mrow[mt][1], mx1);
            const float cr0 = __expf(mrow[mt][0] - mn0);
            const float cr1 = __expf(mrow[mt][1] - mn1);

            float ls0 = 0.0f, ls1 = 0.0f;
            const int r = wid * 32 + mt * 16 + g;
            #pragma unroll
            for (int nt = 0; nt < 8; ++nt) {
                float p0 = __expf(sc[nt][0] - mn0);
                float p1 = __expf(sc[nt][1] - mn0);
                float p2 = __expf(sc[nt][2] - mn1);
                float p3 = __expf(sc[nt][3] - mn1);
                ls0 += p0 + p1;
                ls1 += p2 + p3;
                float2 w0, w1;
                w0.x = __uint_as_float(f2tf32(p0));
                w0.y = __uint_as_float(f2tf32(p1));
                w1.x = __uint_as_float(f2tf32(p2));
                w1.y = __uint_as_float(f2tf32(p3));
                *(float2*)&Ps[r * PSTR + nt * 8 + 2 * t] = w0;
                *(float2*)&Ps[(r + 8) * PSTR + nt * 8 + 2 * t] = w1;
            }
            #pragma unroll
            for (int s = 1; s < 4; s <<= 1) {
                ls0 += __shfl_xor_sync(0xffffffffu, ls0, s);
                ls1 += __shfl_xor_sync(0xffffffffu, ls1, s);
            }
            lrow2[mt][0] = lrow2[mt][0] * cr0 + ls0;
            lrow2[mt][1] = lrow2[mt][1] * cr1 + ls1;
            mrow[mt][0] = mn0;
            mrow[mt][1] = mn1;
            #pragma unroll
            for (int nv = 0; nv < 8; ++nv) {
                o[mt][nv][0] *= cr0; o[mt][nv][1] *= cr0;
                o[mt][nv][2] *= cr1; o[mt][nv][3] *= cr1;
            }
        }
        __syncwarp();

        // ---- O += P @ V : ldmatrix for P a-frags and V b-frags ----
        #pragma unroll
        for (int kt = 0; kt < 8; ++kt) {
            uint32_t pf[2][4];
            ldsm4(pf[0], ps_base + (kt * 8) * 4);
            ldsm4(pf[1], ps_base + (16 * PSTR + kt * 8) * 4);
            #pragma unroll
            for (int nv2 = 0; nv2 < 4; ++nv2) {
                uint32_t bv[4];
                ldsm4(bv, vs_base + (nv2 * 16 * VSTR + kt * 8) * 4);
                mma_tf32(o[0][nv2 * 2 + 0], pf[0], bv);
                mma_tf32(o[1][nv2 * 2 + 0], pf[1], bv);
                mma_tf32(o[0][nv2 * 2 + 1], pf[0], bv + 2);
                mma_tf32(o[1][nv2 * 2 + 1], pf[1], bv + 2);
            }
        }
        __syncthreads();
    }

    // ---- epilogue: divide by row sums, write [B, S, D] ----
    #pragma unroll
    for (int mt = 0; mt < 2; ++mt) {
        const float inv0 = 1.0f / lrow2[mt][0];
        const float inv1 = 1.0f / lrow2[mt][1];
        const int srow = q0 + wid * 32 + mt * 16 + g;
        #pragma unroll
        for (int nv = 0; nv < 8; ++nv) {
            const int d0 = h * 64 + nv * 8 + 2 * t;
            float2 v0, v1;
            v0.x = o[mt][nv][0] * inv0; v0.y = o[mt][nv][1] * inv0;
            v1.x = o[mt][nv][2] * inv1; v1.y = o[mt][nv][3] * inv1;
            *(float2*)&out[((long long)(b * kS + srow)) * kD + d0] = v0;
            *(float2*)&out[((long long)(b * kS + srow + 8)) * kD + d0] = v1;
        }
    }
}

// ======================= launch =======================
extern "C" void kernel_launch(void* const* d_in, const int* in_sizes, int n_in,
                              void* d_out, int out_size)
{
    (void)in_sizes; (void)n_in; (void)out_size;
    const float* X    = (const float*)d_in[0];
    const float* mask = (const float*)d_in[1];
    const float* Wq   = (const float*)d_in[2];
    const float* bq   = (const float*)d_in[3];
    const float* Wk   = (const float*)d_in[4];
    const float* bk   = (const float*)d_in[5];
    const float* Wv   = (const float*)d_in[6];
    const float* bv   = (const float*)d_in[7];
    float* out = (float*)d_out;

    cudaFuncSetAttribute(qkv_kernel, cudaFuncAttributeMaxDynamicSharedMemorySize,
                         GEMM_SMEM_BYTES);
    cudaFuncSetAttribute(attn_kernel, cudaFuncAttributeMaxDynamicSharedMemorySize,
                         ATTN_SMEM_BYTES);

    qkv_kernel<<<dim3(kD / BN, kM / BM, 3), 256, GEMM_SMEM_BYTES>>>(
        X, Wq, bq, Wk, bk, Wv, bv);
    attn_kernel<<<dim3(kS / 128, kB * kH), 128, ATTN_SMEM_BYTES>>>(mask, out);
}

// round 5
// speedup vs baseline: 1.4913x; 1.0438x over previous
#include <cuda_runtime.h>
#include <cstdint>

#define DEVINL __device__ __forceinline__

constexpr int kB = 4, kS = 2048, kD = 1024, kH = 16, kHD = 64;
constexpr int kM = kB * kS;  // 8192 rows for QKV GEMM

// Scratch (values stored PRE-ROUNDED to tf32 bit patterns):
// g_q, g_k : [B, H, S, hd]   g_v : [B, H, hd, S] (transposed for ldmatrix PV)
__device__ float g_q[(long long)kB * kH * kS * kHD];
__device__ float g_k[(long long)kB * kH * kS * kHD];
__device__ float g_v[(long long)kB * kH * kS * kHD];
// Prep outputs: rounded X, rounded W^T ([n][k], rounded) for ldmatrix B-frags.
__device__ float g_x[(long long)kM * kD];
__device__ float g_wt[3ll * kD * kD];

DEVINL uint32_t smem_u32(const void* p) {
    return (uint32_t)__cvta_generic_to_shared(p);
}
DEVINL void cp_async16(uint32_t dst, const void* src) {
    asm volatile("cp.async.cg.shared.global [%0], [%1], 16;\n" ::"r"(dst), "l"(src));
}
DEVINL void cp_commit() { asm volatile("cp.async.commit_group;\n" ::: "memory"); }
template <int N> DEVINL void cp_wait() {
    asm volatile("cp.async.wait_group %0;\n" ::"n"(N) : "memory");
}

// Round-to-nearest tf32 (rna avoids the -0.5ulp truncation bias).
DEVINL uint32_t f2tf32(float f) {
    uint32_t r;
    asm("cvt.rna.tf32.f32 %0, %1;\n" : "=r"(r) : "f"(f));
    return r;
}

DEVINL void mma_tf32(float* c, const uint32_t* a, const uint32_t* b) {
    asm volatile(
        "mma.sync.aligned.m16n8k8.row.col.f32.tf32.tf32.f32 "
        "{%0,%1,%2,%3}, {%4,%5,%6,%7}, {%8,%9}, {%0,%1,%2,%3};\n"
        : "+f"(c[0]), "+f"(c[1]), "+f"(c[2]), "+f"(c[3])
        : "r"(a[0]), "r"(a[1]), "r"(a[2]), "r"(a[3]), "r"(b[0]), "r"(b[1]));
}

DEVINL void ldsm4(uint32_t* r, uint32_t addr) {
    asm volatile(
        "ldmatrix.sync.aligned.m8n8.x4.shared.b16 {%0,%1,%2,%3}, [%4];\n"
        : "=r"(r[0]), "=r"(r[1]), "=r"(r[2]), "=r"(r[3]) : "r"(addr));
}

// ======================= Stage 0: prep =======================
// W^T (rounded): g_wt[z][n][k] = round(W_z[k][n])
__global__ __launch_bounds__(256) void prep_wt_kernel(
    const float* __restrict__ Wq, const float* __restrict__ Wk,
    const float* __restrict__ Wv)
{
    __shared__ float t[32][33];
    const int z = blockIdx.z;
    const float* W = (z == 0) ? Wq : (z == 1) ? Wk : Wv;
    float* outp = g_wt + (long long)z * kD * kD;
    const int n0 = blockIdx.x * 32, k0 = blockIdx.y * 32;
    const int tx = threadIdx.x & 31, ty = threadIdx.x >> 5;  // 32 x 8
    #pragma unroll
    for (int r = ty; r < 32; r += 8)
        t[r][tx] = W[(long long)(k0 + r) * kD + n0 + tx];
    __syncthreads();
    #pragma unroll
    for (int r = ty; r < 32; r += 8)
        outp[(long long)(n0 + r) * kD + k0 + tx] =
            __uint_as_float(f2tf32(t[tx][r]));
}

// round(X) -> g_x
__global__ __launch_bounds__(256) void prep_x_kernel(const float* __restrict__ X)
{
    const long long n4 = (long long)kM * kD / 4;
    const float4* src = (const float4*)X;
    float4* dst = (float4*)g_x;
    for (long long i = blockIdx.x * 256 + threadIdx.x; i < n4;
         i += (long long)gridDim.x * 256) {
        float4 v = src[i];
        v.x = __uint_as_float(f2tf32(v.x));
        v.y = __uint_as_float(f2tf32(v.y));
        v.z = __uint_as_float(f2tf32(v.z));
        v.w = __uint_as_float(f2tf32(v.w));
        dst[i] = v;
    }
}

// ======================= Stage 1: QKV projections =======================
// C[8192,1024] = g_x @ g_wt[z]^T + bias. Tile 128x128x32, 8 warps (2m x 4n),
// all fragments via ldmatrix.x4 on pre-rounded data (zero mainloop cvts).
constexpr int BM = 128, BN = 128, BK = 32;
constexpr int ASTR = 36;   // mod 32 = 4 -> conflict-free ldmatrix row rotation
constexpr int BSTR = 36;
constexpr int GEMM_SMEM_BYTES = 2 * (BM * ASTR + BN * BSTR) * 4;  // 73728

__global__ __launch_bounds__(256) void qkv_kernel(
    const float* __restrict__ bq, const float* __restrict__ bk,
    const float* __restrict__ bv)
{
    extern __shared__ float sm[];
    float* As  = sm;                          // 2 x 128 x ASTR (m rows x k)
    float* Bsh = sm + 2 * BM * ASTR;          // 2 x 128 x BSTR (n rows x k)

    const int z = blockIdx.z;
    const float* bia = (z == 0) ? bq : (z == 1) ? bk : bv;
    float* outp      = (z == 0) ? g_q : (z == 1) ? g_k : g_v;
    const float scl  = (z == 0) ? 0.125f : 1.0f;  // hd^-0.5 folded into Q
    const float* wt  = g_wt + (long long)z * kD * kD;

    const int bm = blockIdx.y * BM;
    const int bn = blockIdx.x * BN;
    const int tid = threadIdx.x;
    const int wid = tid >> 5, lane = tid & 31;
    const int wm = (wid >> 2) * 64, wn = (wid & 3) * 32;
    const int g = lane >> 2, t = lane & 3;
    const int lrow = lane & 7;
    const int lt8 = (lane >> 3) & 1, lt16 = (lane >> 4) & 1;

    // ldmatrix per-lane offsets (floats), validated patterns from R3:
    // A a-frag (16 rows x 8 k):   rows lrow+lt8*8, col-half lt16*4
    const int aoff = (lrow + lt8 * 8) * ASTR + lt16 * 4;
    // B b-frag pair (8 n x 16 k): rows lrow, cols lt8*4 + lt16*8
    const int boff = lrow * BSTR + lt8 * 4 + lt16 * 8;

    float acc[4][4][4];
    #pragma unroll
    for (int mt = 0; mt < 4; ++mt)
        #pragma unroll
        for (int nt = 0; nt < 4; ++nt)
            #pragma unroll
            for (int i = 0; i < 4; ++i) acc[mt][nt][i] = 0.0f;

    auto load_stage = [&](int st, int k0) {
        float* A  = As  + st * BM * ASTR;
        float* Bm = Bsh + st * BN * BSTR;
        #pragma unroll
        for (int c = 0; c < 4; ++c) {   // 128 rows x 8 chunks = 1024 per tile
            const int ch = tid + c * 256;
            const int r = ch >> 3, cc = (ch & 7) * 4;
            cp_async16(smem_u32(A + r * ASTR + cc),
                       g_x + (long long)(bm + r) * kD + k0 + cc);
            cp_async16(smem_u32(Bm + r * BSTR + cc),
                       wt + (long long)(bn + r) * kD + k0 + cc);
        }
        cp_commit();
    };

    load_stage(0, 0);
    #pragma unroll 1
    for (int i = 0; i < kD / BK; ++i) {
        const int st = i & 1;
        if (i + 1 < kD / BK) {
            load_stage(st ^ 1, (i + 1) * BK);
            cp_wait<1>();
        } else {
            cp_wait<0>();
        }
        __syncthreads();

        const uint32_t a_lane =
            smem_u32(As + st * BM * ASTR + wm * ASTR) + aoff * 4;
        const uint32_t b_lane =
            smem_u32(Bsh + st * BN * BSTR + wn * BSTR) + boff * 4;

        #pragma unroll
        for (int kt2 = 0; kt2 < 2; ++kt2) {  // two 16-wide k sub-blocks
            uint32_t af[4][8];
            #pragma unroll
            for (int mt = 0; mt < 4; ++mt) {
                ldsm4(af[mt],     a_lane + (mt * 16 * ASTR + kt2 * 16) * 4);
                ldsm4(af[mt] + 4, a_lane + (mt * 16 * ASTR + kt2 * 16 + 8) * 4);
            }
            #pragma unroll
            for (int nt = 0; nt < 4; ++nt) {
                uint32_t bk2[4];
                ldsm4(bk2, b_lane + (nt * 8 * BSTR + kt2 * 16) * 4);
                #pragma unroll
                for (int mt = 0; mt < 4; ++mt) {
                    mma_tf32(acc[mt][nt], af[mt],     bk2);
                    mma_tf32(acc[mt][nt], af[mt] + 4, bk2 + 2);
                }
            }
        }
        __syncthreads();  // all warps done reading stage st before overwrite
    }

    // Epilogue: + bias, * scale, tf32-round, scatter (V transposed [d][s]).
    #pragma unroll
    for (int mt = 0; mt < 4; ++mt) {
        #pragma unroll
        for (int nt = 0; nt < 4; ++nt) {
            const int col = bn + wn + nt * 8 + 2 * t;  // even
            const int hh = col >> 6, d0 = col & 63;
            const float b0 = bia[col], b1 = bia[col + 1];
            #pragma unroll
            for (int rr = 0; rr < 2; ++rr) {
                const int m = bm + wm + mt * 16 + g + rr * 8;
                const int bb = m >> 11, ss = m & 2047;
                const float x0 = __uint_as_float(f2tf32((acc[mt][nt][rr * 2 + 0] + b0) * scl));
                const float x1 = __uint_as_float(f2tf32((acc[mt][nt][rr * 2 + 1] + b1) * scl));
                if (z < 2) {
                    float2 v; v.x = x0; v.y = x1;
                    *(float2*)&outp[((long long)(bb * kH + hh) * kS + ss) * kHD + d0] = v;
                } else {  // V transposed: [b,h][d][s]
                    const long long base = ((long long)(bb * kH + hh) * kHD + d0) * kS + ss;
                    outp[base] = x0;
                    outp[base + kS] = x1;
                }
            }
        }
    }
}

// ======================= Stage 2: flash attention =======================
// (byte-identical to R3 — consumes pre-rounded g_q/g_k/g_v)
constexpr int KSTR = 68;
constexpr int VSTR = 68;
constexpr int PSTR = 68;
constexpr int ATTN_SMEM_BYTES =
    (2 * 64 * KSTR + 2 * 64 * VSTR + 128 * PSTR + 128) * 4;  // 104960

__global__ __launch_bounds__(128) void attn_kernel(
    const float* __restrict__ mask, float* __restrict__ out)
{
    extern __shared__ float sm[];
    float* Kbuf = sm;
    float* Vbuf = Kbuf + 2 * 64 * KSTR;
    float* Ps   = Vbuf + 2 * 64 * VSTR;
    float* Msk  = Ps + 128 * PSTR;

    const int bh = blockIdx.y;
    const int b = bh >> 4, h = bh & 15;
    const int q0 = blockIdx.x * 128;
    const int tid = threadIdx.x, wid = tid >> 5, lane = tid & 31;
    const int g = lane >> 2, t = lane & 3;
    const int lrow = lane & 7;
    const int lt8 = (lane >> 3) & 1, lt16 = (lane >> 4) & 1;

    const float* qptr = g_q + ((long long)bh * kS + q0) * kHD;
    const float* kptr = g_k + (long long)bh * kS * kHD;
    const float* vptr = g_v + (long long)bh * kHD * kS;  // [d][s]

    const int koff = lrow * KSTR + lt8 * 4 + lt16 * 8;
    const int voff = (lrow + lt16 * 8) * VSTR + lt8 * 4;
    const int poff = (wid * 32 + lrow + lt8 * 8) * PSTR + lt16 * 4;

    uint32_t qf[2][8][4];
    #pragma unroll 1
    for (int half = 0; half < 2; ++half) {
        if (half) __syncthreads();
        #pragma unroll
        for (int i = 0; i < 8; ++i) {
            int lin = tid + i * 128;
            int r = lin >> 4, c = (lin & 15) * 4;
            *(float4*)&Kbuf[r * KSTR + c] =
                *(const float4*)&qptr[(long long)(half * 64 + r) * kHD + c];
        }
        __syncthreads();
        if ((wid >> 1) == half) {
            const int lr = (wid & 1) * 32 + g;
            #pragma unroll
            for (int mt = 0; mt < 2; ++mt)
                #pragma unroll
                for (int kt = 0; kt < 8; ++kt) {
                    const float* qp = Kbuf + (lr + mt * 16) * KSTR + kt * 8 + t;
                    qf[mt][kt][0] = __float_as_uint(qp[0]);
                    qf[mt][kt][1] = __float_as_uint(qp[8 * KSTR]);
                    qf[mt][kt][2] = __float_as_uint(qp[4]);
                    qf[mt][kt][3] = __float_as_uint(qp[8 * KSTR + 4]);
                }
        }
    }
    __syncthreads();

    auto prefetch = [&](int st, int k0) {
        float* Kd = Kbuf + st * 64 * KSTR;
        float* Vd = Vbuf + st * 64 * VSTR;
        #pragma unroll
        for (int i = 0; i < 8; ++i) {
            int ch = tid + i * 128;
            int r = ch >> 4, c4 = (ch & 15) * 4;
            cp_async16(smem_u32(Kd + r * KSTR + c4),
                       kptr + (long long)(k0 + r) * kHD + c4);
            cp_async16(smem_u32(Vd + r * VSTR + c4),
                       vptr + (long long)r * kS + k0 + c4);
        }
        if (tid < 16)
            cp_async16(smem_u32(Msk + st * 64 + tid * 4),
                       mask + b * kS + k0 + tid * 4);
        cp_commit();
    };

    float o[2][8][4];
    #pragma unroll
    for (int mt = 0; mt < 2; ++mt)
        #pragma unroll
        for (int nv = 0; nv < 8; ++nv)
            #pragma unroll
            for (int i = 0; i < 4; ++i) o[mt][nv][i] = 0.0f;
    float mrow[2][2] = {{-1e30f, -1e30f}, {-1e30f, -1e30f}};
    float lrow2[2][2] = {{0.0f, 0.0f}, {0.0f, 0.0f}};

    prefetch(0, 0);

    #pragma unroll 1
    for (int it = 0; it < kS / 64; ++it) {
        const int st = it & 1;
        if (it + 1 < kS / 64) {
            prefetch(st ^ 1, (it + 1) * 64);
            cp_wait<1>();
        } else {
            cp_wait<0>();
        }
        __syncthreads();

        const float* Ks = Kbuf + st * 64 * KSTR;
        const float* Vs = Vbuf + st * 64 * VSTR;
        const float* Ms = Msk + st * 64;
        const uint32_t ks_base = smem_u32(Ks + koff);
        const uint32_t vs_base = smem_u32(Vs + voff);
        const uint32_t ps_base = smem_u32(Ps) + poff * 4;

        #pragma unroll
        for (int mt = 0; mt < 2; ++mt) {
            float sc[8][4];
            #pragma unroll
            for (int nt = 0; nt < 8; ++nt) {
                sc[nt][0] = sc[nt][1] = sc[nt][2] = sc[nt][3] = 0.0f;
                #pragma unroll
                for (int kt2 = 0; kt2 < 4; ++kt2) {
                    uint32_t bk2[4];
                    ldsm4(bk2, ks_base + (nt * 8 * KSTR + kt2 * 16) * 4);
                    mma_tf32(sc[nt], qf[mt][2 * kt2], bk2);
                    mma_tf32(sc[nt], qf[mt][2 * kt2 + 1], bk2 + 2);
                }
            }
            #pragma unroll
            for (int nt = 0; nt < 8; ++nt) {
                const float m0 = Ms[nt * 8 + 2 * t], m1 = Ms[nt * 8 + 2 * t + 1];
                sc[nt][0] += m0; sc[nt][1] += m1;
                sc[nt][2] += m0; sc[nt][3] += m1;
            }
            float mx0 = -1e30f, mx1 = -1e30f;
            #pragma unroll
            for (int nt = 0; nt < 8; ++nt) {
                mx0 = fmaxf(mx0, fmaxf(sc[nt][0], sc[nt][1]));
                mx1 = fmaxf(mx1, fmaxf(sc[nt][2], sc[nt][3]));
            }
            #pragma unroll
            for (int s = 1; s < 4; s <<= 1) {
                mx0 = fmaxf(mx0, __shfl_xor_sync(0xffffffffu, mx0, s));
                mx1 = fmaxf(mx1, __shfl_xor_sync(0xffffffffu, mx1, s));
            }
            const float mn0 = fmaxf(mrow[mt][0], mx0);
            const float mn1 = fmaxf(mrow[mt][1], mx1);
            const float cr0 = __expf(mrow[mt][0] - mn0);
            const float cr1 = __expf(mrow[mt][1] - mn1);

            float ls0 = 0.0f, ls1 = 0.0f;
            const int r = wid * 32 + mt * 16 + g;
            #pragma unroll
            for (int nt = 0; nt < 8; ++nt) {
                float p0 = __expf(sc[nt][0] - mn0);
                float p1 = __expf(sc[nt][1] - mn0);
                float p2 = __expf(sc[nt][2] - mn1);
                float p3 = __expf(sc[nt][3] - mn1);
                ls0 += p0 + p1;
                ls1 += p2 + p3;
                float2 w0, w1;
                w0.x = __uint_as_float(f2tf32(p0));
                w0.y = __uint_as_float(f2tf32(p1));
                w1.x = __uint_as_float(f2tf32(p2));
                w1.y = __uint_as_float(f2tf32(p3));
                *(float2*)&Ps[r * PSTR + nt * 8 + 2 * t] = w0;
                *(float2*)&Ps[(r + 8) * PSTR + nt * 8 + 2 * t] = w1;
            }
            #pragma unroll
            for (int s = 1; s < 4; s <<= 1) {
                ls0 += __shfl_xor_sync(0xffffffffu, ls0, s);
                ls1 += __shfl_xor_sync(0xffffffffu, ls1, s);
            }
            lrow2[mt][0] = lrow2[mt][0] * cr0 + ls0;
            lrow2[mt][1] = lrow2[mt][1] * cr1 + ls1;
            mrow[mt][0] = mn0;
            mrow[mt][1] = mn1;
            #pragma unroll
            for (int nv = 0; nv < 8; ++nv) {
                o[mt][nv][0] *= cr0; o[mt][nv][1] *= cr0;
                o[mt][nv][2] *= cr1; o[mt][nv][3] *= cr1;
            }
        }
        __syncwarp();

        #pragma unroll
        for (int kt = 0; kt < 8; ++kt) {
            uint32_t pf[2][4];
            ldsm4(pf[0], ps_base + (kt * 8) * 4);
            ldsm4(pf[1], ps_base + (16 * PSTR + kt * 8) * 4);
            #pragma unroll
            for (int nv2 = 0; nv2 < 4; ++nv2) {
                uint32_t bv[4];
                ldsm4(bv, vs_base + (nv2 * 16 * VSTR + kt * 8) * 4);
                mma_tf32(o[0][nv2 * 2 + 0], pf[0], bv);
                mma_tf32(o[1][nv2 * 2 + 0], pf[1], bv);
                mma_tf32(o[0][nv2 * 2 + 1], pf[0], bv + 2);
                mma_tf32(o[1][nv2 * 2 + 1], pf[1], bv + 2);
            }
        }
        __syncthreads();
    }

    #pragma unroll
    for (int mt = 0; mt < 2; ++mt) {
        const float inv0 = 1.0f / lrow2[mt][0];
        const float inv1 = 1.0f / lrow2[mt][1];
        const int srow = q0 + wid * 32 + mt * 16 + g;
        #pragma unroll
        for (int nv = 0; nv < 8; ++nv) {
            const int d0 = h * 64 + nv * 8 + 2 * t;
            float2 v0, v1;
            v0.x = o[mt][nv][0] * inv0; v0.y = o[mt][nv][1] * inv0;
            v1.x = o[mt][nv][2] * inv1; v1.y = o[mt][nv][3] * inv1;
            *(float2*)&out[((long long)(b * kS + srow)) * kD + d0] = v0;
            *(float2*)&out[((long long)(b * kS + srow + 8)) * kD + d0] = v1;
        }
    }
}

// ======================= launch =======================
extern "C" void kernel_launch(void* const* d_in, const int* in_sizes, int n_in,
                              void* d_out, int out_size)
{
    (void)in_sizes; (void)n_in; (void)out_size;
    const float* X    = (const float*)d_in[0];
    const float* mask = (const float*)d_in[1];
    const float* Wq   = (const float*)d_in[2];
    const float* bq   = (const float*)d_in[3];
    const float* Wk   = (const float*)d_in[4];
    const float* bk   = (const float*)d_in[5];
    const float* Wv   = (const float*)d_in[6];
    const float* bv   = (const float*)d_in[7];
    float* out = (float*)d_out;

    cudaFuncSetAttribute(qkv_kernel, cudaFuncAttributeMaxDynamicSharedMemorySize,
                         GEMM_SMEM_BYTES);
    cudaFuncSetAttribute(attn_kernel, cudaFuncAttributeMaxDynamicSharedMemorySize,
                         ATTN_SMEM_BYTES);

    prep_wt_kernel<<<dim3(32, 32, 3), 256>>>(Wq, Wk, Wv);
    prep_x_kernel<<<1024, 256>>>(X);
    qkv_kernel<<<dim3(kD / BN, kM / BM, 3), 256, GEMM_SMEM_BYTES>>>(bq, bk, bv);
    attn_kernel<<<dim3(kS / 128, kB * kH), 128, ATTN_SMEM_BYTES>>>(mask, out);
}

// round 7
// speedup vs baseline: 2.6046x; 1.7465x over previous
#include <cuda_runtime.h>
#include <cuda_fp16.h>
#include <cstdint>

#define DEVINL __device__ __forceinline__

constexpr int kB = 4, kS = 2048, kD = 1024, kH = 16, kHD = 64;
constexpr int kM = kB * kS;  // 8192 rows for QKV GEMM

// All fp16 (same 10-bit mantissa as tf32 -> same rounding error as R3/R5):
// g_q, g_k : [B,H][S][64]   g_v : [B,H][64][S] (V^T)   g_x : rounded X
// g_wt : rounded W^T ([n][k]) per z
__device__ __half g_q[(long long)kB * kH * kS * kHD];
__device__ __half g_k[(long long)kB * kH * kS * kHD];
__device__ __half g_v[(long long)kB * kH * kS * kHD];
__device__ __half g_x[(long long)kM * kD];
__device__ __half g_wt[3ll * kD * kD];

DEVINL uint32_t smem_u32(const void* p) {
    return (uint32_t)__cvta_generic_to_shared(p);
}
DEVINL void cp_async16(uint32_t dst, const void* src) {
    asm volatile("cp.async.cg.shared.global [%0], [%1], 16;\n" ::"r"(dst), "l"(src));
}
DEVINL void cp_commit() { asm volatile("cp.async.commit_group;\n" ::: "memory"); }
template <int N> DEVINL void cp_wait() {
    asm volatile("cp.async.wait_group %0;\n" ::"n"(N) : "memory");
}

DEVINL uint32_t packh2(float lo, float hi) {
    __half2 h = __floats2half2_rn(lo, hi);
    return *reinterpret_cast<uint32_t*>(&h);
}

DEVINL void mma_f16(float* c, const uint32_t* a, uint32_t b0, uint32_t b1) {
    asm volatile(
        "mma.sync.aligned.m16n8k16.row.col.f32.f16.f16.f32 "
        "{%0,%1,%2,%3}, {%4,%5,%6,%7}, {%8,%9}, {%0,%1,%2,%3};\n"
        : "+f"(c[0]), "+f"(c[1]), "+f"(c[2]), "+f"(c[3])
        : "r"(a[0]), "r"(a[1]), "r"(a[2]), "r"(a[3]), "r"(b0), "r"(b1));
}

DEVINL void ldsm4(uint32_t* r, uint32_t addr) {
    asm volatile(
        "ldmatrix.sync.aligned.m8n8.x4.shared.b16 {%0,%1,%2,%3}, [%4];\n"
        : "=r"(r[0]), "=r"(r[1]), "=r"(r[2]), "=r"(r[3]) : "r"(addr));
}

// ======================= Stage 0: prep =======================
// W^T (rounded fp16): g_wt[z][n][k] = fp16(W_z[k][n])
__global__ __launch_bounds__(256) void prep_wt_kernel(
    const float* __restrict__ Wq, const float* __restrict__ Wk,
    const float* __restrict__ Wv)
{
    __shared__ float t[32][33];
    const int z = blockIdx.z;
    const float* W = (z == 0) ? Wq : (z == 1) ? Wk : Wv;
    __half* outp = g_wt + (long long)z * kD * kD;
    const int n0 = blockIdx.x * 32, k0 = blockIdx.y * 32;
    const int tx = threadIdx.x & 31, ty = threadIdx.x >> 5;  // 32 x 8
    #pragma unroll
    for (int r = ty; r < 32; r += 8)
        t[r][tx] = W[(long long)(k0 + r) * kD + n0 + tx];
    __syncthreads();
    #pragma unroll
    for (int r = ty; r < 32; r += 8)
        outp[(long long)(n0 + r) * kD + k0 + tx] = __float2half_rn(t[tx][r]);
}

// fp16(X) -> g_x
__global__ __launch_bounds__(256) void prep_x_kernel(const float* __restrict__ X)
{
    const long long n4 = (long long)kM * kD / 4;
    const float4* src = (const float4*)X;
    uint2* dst = (uint2*)g_x;
    for (long long i = blockIdx.x * 256 + threadIdx.x; i < n4;
         i += (long long)gridDim.x * 256) {
        float4 v = src[i];
        uint2 o;
        o.x = packh2(v.x, v.y);
        o.y = packh2(v.z, v.w);
        dst[i] = o;
    }
}

// ======================= Stage 1: QKV projections (fp16 mma) ============
// C[8192,1024] = g_x @ g_wt[z]^T + bias. Tile 128x128, k-step 64, 8 warps.
constexpr int STRH = 72;  // fp16 stride: 144B rows -> conflict-free ldmatrix
constexpr int GEMM_SMEM_BYTES = 2 * 2 * 128 * STRH * 2;  // 73728

__global__ __launch_bounds__(256) void qkv_kernel(
    const float* __restrict__ bq, const float* __restrict__ bk,
    const float* __restrict__ bv)
{
    extern __shared__ __align__(16) char smraw[];
    __half* As = (__half*)smraw;                 // 2 x 128 x STRH
    __half* Bs = As + 2 * 128 * STRH;            // 2 x 128 x STRH

    const int z = blockIdx.z;
    const float* bia = (z == 0) ? bq : (z == 1) ? bk : bv;
    __half* outp     = (z == 0) ? g_q : (z == 1) ? g_k : g_v;
    const float scl  = (z == 0) ? 0.125f : 1.0f;  // hd^-0.5 folded into Q
    const __half* wt = g_wt + (long long)z * kD * kD;

    const int bm = blockIdx.y * 128;
    const int bn = blockIdx.x * 128;
    const int tid = threadIdx.x;
    const int wid = tid >> 5, lane = tid & 31;
    const int wm = (wid >> 2) * 64, wn = (wid & 3) * 32;
    const int g = lane >> 2, t = lane & 3;
    const int lrow = lane & 7;
    const int lt8 = (lane >> 3) & 1, lt16 = (lane >> 4) & 1;

    float acc[4][4][4];
    #pragma unroll
    for (int mt = 0; mt < 4; ++mt)
        #pragma unroll
        for (int nt = 0; nt < 4; ++nt)
            #pragma unroll
            for (int i = 0; i < 4; ++i) acc[mt][nt][i] = 0.0f;

    auto load_stage = [&](int st, int k0) {
        __half* A  = As + st * 128 * STRH;
        __half* Bm = Bs + st * 128 * STRH;
        #pragma unroll
        for (int c = 0; c < 4; ++c) {   // 128 rows x 8 chunks(16B) per operand
            const int ch = tid + c * 256;
            const int r = ch >> 3, cc = (ch & 7) * 8;
            cp_async16(smem_u32(A + r * STRH + cc),
                       g_x + (long long)(bm + r) * kD + k0 + cc);
            cp_async16(smem_u32(Bm + r * STRH + cc),
                       wt + (long long)(bn + r) * kD + k0 + cc);
        }
        cp_commit();
    };

    load_stage(0, 0);
    #pragma unroll 1
    for (int i = 0; i < 16; ++i) {
        const int st = i & 1;
        if (i + 1 < 16) {
            load_stage(st ^ 1, (i + 1) * 64);
            cp_wait<1>();
        } else {
            cp_wait<0>();
        }
        __syncthreads();

        const uint32_t a_base = smem_u32(As) + st * 128 * STRH * 2 +
            ((wm + lrow + lt8 * 8) * STRH + lt16 * 8) * 2;
        const uint32_t b_base = smem_u32(Bs) + st * 128 * STRH * 2 +
            ((wn + lrow + lt8 * 8) * STRH + lt16 * 8) * 2;

        #pragma unroll
        for (int kc = 0; kc < 4; ++kc) {
            uint32_t af[4][4], bf[2][4];
            #pragma unroll
            for (int mt = 0; mt < 4; ++mt)
                ldsm4(af[mt], a_base + (mt * 16 * STRH + kc * 16) * 2);
            #pragma unroll
            for (int ntp = 0; ntp < 2; ++ntp)
                ldsm4(bf[ntp], b_base + (ntp * 16 * STRH + kc * 16) * 2);
            #pragma unroll
            for (int mt = 0; mt < 4; ++mt)
                #pragma unroll
                for (int ntp = 0; ntp < 2; ++ntp) {
                    mma_f16(acc[mt][ntp * 2 + 0], af[mt], bf[ntp][0], bf[ntp][2]);
                    mma_f16(acc[mt][ntp * 2 + 1], af[mt], bf[ntp][1], bf[ntp][3]);
                }
        }
        __syncthreads();
    }

    // Epilogue: + bias, * scale, fp16-round, scatter (V transposed [d][s]).
    #pragma unroll
    for (int mt = 0; mt < 4; ++mt) {
        #pragma unroll
        for (int nt = 0; nt < 4; ++nt) {
            const int col = bn + wn + nt * 8 + 2 * t;  // even
            const int hh = col >> 6, d0 = col & 63;
            const float b0 = bia[col], b1 = bia[col + 1];
            #pragma unroll
            for (int rr = 0; rr < 2; ++rr) {
                const int m = bm + wm + mt * 16 + g + rr * 8;
                const int bb = m >> 11, ss = m & 2047;
                const __half x0 = __float2half_rn((acc[mt][nt][rr * 2 + 0] + b0) * scl);
                const __half x1 = __float2half_rn((acc[mt][nt][rr * 2 + 1] + b1) * scl);
                if (z < 2) {
                    __half2 v; v.x = x0; v.y = x1;
                    *(__half2*)&outp[((long long)(bb * kH + hh) * kS + ss) * kHD + d0] = v;
                } else {  // V^T: [b,h][d][s]
                    const long long base = ((long long)(bb * kH + hh) * kHD + d0) * kS + ss;
                    outp[base] = x0;
                    outp[base + kS] = x1;
                }
            }
        }
    }
}

// ======================= Stage 2: flash attention (fp16 mma) ============
// CTA = (b,h, 128 q-rows), 4 warps x 32 rows (2 m-tiles). P never touches
// smem: f32 S c-frags pack via cvt.rn.f16x2 directly into m16n8k16 a-frags.
constexpr int ATTN_SMEM_BYTES = 2 * (2 * 64 * STRH * 2) + 2 * 64 * 4;  // 37376

__global__ __launch_bounds__(128) void attn_kernel(
    const float* __restrict__ mask, float* __restrict__ out)
{
    extern __shared__ __align__(16) char smraw[];
    __half* Kb = (__half*)smraw;          // 2 x 64 x STRH  (rows s, cols d)
    __half* Vb = Kb + 2 * 64 * STRH;      // 2 x 64 x STRH  (rows d, cols s)
    float* Msk = (float*)(Vb + 2 * 64 * STRH);  // 2 x 64

    const int bh = blockIdx.y;
    const int b = bh >> 4, h = bh & 15;
    const int q0 = blockIdx.x * 128;
    const int tid = threadIdx.x, wid = tid >> 5, lane = tid & 31;
    const int g = lane >> 2, t = lane & 3;
    const int lrow = lane & 7;
    const int lt8 = (lane >> 3) & 1, lt16 = (lane >> 4) & 1;

    const __half* qptr = g_q + ((long long)bh * kS + q0) * kHD;
    const __half* kptr = g_k + (long long)bh * kS * kHD;
    const __half* vptr = g_v + (long long)bh * kHD * kS;  // [d][s]

    // ---- stage Q (128 x 64 fp16) through Kb, grab a-frags, release ----
    #pragma unroll
    for (int i = 0; i < 8; ++i) {
        const int ch = tid + i * 128;
        const int r = ch >> 3, c = (ch & 7) * 8;
        *(uint4*)&Kb[r * STRH + c] = *(const uint4*)&qptr[(long long)r * kHD + c];
    }
    __syncthreads();
    uint32_t qf[2][4][4];
    {
        const uint32_t qbase = smem_u32(Kb) +
            ((wid * 32 + lrow + lt8 * 8) * STRH + lt16 * 8) * 2;
        #pragma unroll
        for (int mt = 0; mt < 2; ++mt)
            #pragma unroll
            for (int kc = 0; kc < 4; ++kc)
                ldsm4(qf[mt][kc], qbase + (mt * 16 * STRH + kc * 16) * 2);
    }
    __syncthreads();

    auto prefetch = [&](int st, int k0) {
        __half* Kd = Kb + st * 64 * STRH;
        __half* Vd = Vb + st * 64 * STRH;
        #pragma unroll
        for (int i = 0; i < 4; ++i) {
            const int ch = tid + i * 128;       // 512 chunks per operand
            const int r = ch >> 3, c = (ch & 7) * 8;
            cp_async16(smem_u32(Kd + r * STRH + c),
                       kptr + (long long)(k0 + r) * kHD + c);
            cp_async16(smem_u32(Vd + r * STRH + c),
                       vptr + (long long)r * kS + k0 + c);
        }
        if (tid < 16)
            cp_async16(smem_u32(Msk + st * 64 + tid * 4),
                       mask + b * kS + k0 + tid * 4);
        cp_commit();
    };

    float o[2][8][4];
    #pragma unroll
    for (int mt = 0; mt < 2; ++mt)
        #pragma unroll
        for (int nv = 0; nv < 8; ++nv)
            #pragma unroll
            for (int i = 0; i < 4; ++i) o[mt][nv][i] = 0.0f;
    float mrow[2][2] = {{-1e30f, -1e30f}, {-1e30f, -1e30f}};
    float lsum[2][2] = {{0.0f, 0.0f}, {0.0f, 0.0f}};

    prefetch(0, 0);

    #pragma unroll 1
    for (int it = 0; it < kS / 64; ++it) {
        const int st = it & 1;
        if (it + 1 < kS / 64) {
            prefetch(st ^ 1, (it + 1) * 64);
            cp_wait<1>();
        } else {
            cp_wait<0>();
        }
        __syncthreads();

        const uint32_t kbase = smem_u32(Kb) + st * 64 * STRH * 2 +
            ((lrow + lt8 * 8) * STRH + lt16 * 8) * 2;
        const uint32_t vbase = smem_u32(Vb) + st * 64 * STRH * 2 +
            ((lrow + lt8 * 8) * STRH + lt16 * 8) * 2;
        const float* Ms = Msk + st * 64;

        #pragma unroll
        for (int mt = 0; mt < 2; ++mt) {
            // ---- S = Q @ K^T ----
            float sc[8][4];
            #pragma unroll
            for (int nt = 0; nt < 8; ++nt)
                sc[nt][0] = sc[nt][1] = sc[nt][2] = sc[nt][3] = 0.0f;
            #pragma unroll
            for (int kc = 0; kc < 4; ++kc)
                #pragma unroll
                for (int ntp = 0; ntp < 4; ++ntp) {
                    uint32_t bk[4];
                    ldsm4(bk, kbase + (ntp * 16 * STRH + kc * 16) * 2);
                    mma_f16(sc[ntp * 2 + 0], qf[mt][kc], bk[0], bk[2]);
                    mma_f16(sc[ntp * 2 + 1], qf[mt][kc], bk[1], bk[3]);
                }

            // ---- + mask, online softmax (exp in place) ----
            #pragma unroll
            for (int nt = 0; nt < 8; ++nt) {
                const float m0 = Ms[nt * 8 + 2 * t], m1 = Ms[nt * 8 + 2 * t + 1];
                sc[nt][0] += m0; sc[nt][1] += m1;
                sc[nt][2] += m0; sc[nt][3] += m1;
            }
            float mx0 = -1e30f, mx1 = -1e30f;
            #pragma unroll
            for (int nt = 0; nt < 8; ++nt) {
                mx0 = fmaxf(mx0, fmaxf(sc[nt][0], sc[nt][1]));
                mx1 = fmaxf(mx1, fmaxf(sc[nt][2], sc[nt][3]));
            }
            #pragma unroll
            for (int s = 1; s < 4; s <<= 1) {
                mx0 = fmaxf(mx0, __shfl_xor_sync(0xffffffffu, mx0, s));
                mx1 = fmaxf(mx1, __shfl_xor_sync(0xffffffffu, mx1, s));
            }
            const float mn0 = fmaxf(mrow[mt][0], mx0);
            const float mn1 = fmaxf(mrow[mt][1], mx1);
            const float cr0 = __expf(mrow[mt][0] - mn0);
            const float cr1 = __expf(mrow[mt][1] - mn1);

            float ls0 = 0.0f, ls1 = 0.0f;
            #pragma unroll
            for (int nt = 0; nt < 8; ++nt) {
                sc[nt][0] = __expf(sc[nt][0] - mn0);
                sc[nt][1] = __expf(sc[nt][1] - mn0);
                sc[nt][2] = __expf(sc[nt][2] - mn1);
                sc[nt][3] = __expf(sc[nt][3] - mn1);
                ls0 += sc[nt][0] + sc[nt][1];
                ls1 += sc[nt][2] + sc[nt][3];
            }
            #pragma unroll
            for (int s = 1; s < 4; s <<= 1) {
                ls0 += __shfl_xor_sync(0xffffffffu, ls0, s);
                ls1 += __shfl_xor_sync(0xffffffffu, ls1, s);
            }
            lsum[mt][0] = lsum[mt][0] * cr0 + ls0;
            lsum[mt][1] = lsum[mt][1] * cr1 + ls1;
            mrow[mt][0] = mn0;
            mrow[mt][1] = mn1;
            #pragma unroll
            for (int nv = 0; nv < 8; ++nv) {
                o[mt][nv][0] *= cr0; o[mt][nv][1] *= cr0;
                o[mt][nv][2] *= cr1; o[mt][nv][3] *= cr1;
            }

            // ---- O += P @ V : P packs straight from registers ----
            #pragma unroll
            for (int kc = 0; kc < 4; ++kc) {
                uint32_t pf[4];
                pf[0] = packh2(sc[2 * kc][0],     sc[2 * kc][1]);
                pf[1] = packh2(sc[2 * kc][2],     sc[2 * kc][3]);
                pf[2] = packh2(sc[2 * kc + 1][0], sc[2 * kc + 1][1]);
                pf[3] = packh2(sc[2 * kc + 1][2], sc[2 * kc + 1][3]);
                #pragma unroll
                for (int nvp = 0; nvp < 4; ++nvp) {
                    uint32_t bv[4];
                    ldsm4(bv, vbase + (nvp * 16 * STRH + kc * 16) * 2);
                    mma_f16(o[mt][nvp * 2 + 0], pf, bv[0], bv[2]);
                    mma_f16(o[mt][nvp * 2 + 1], pf, bv[1], bv[3]);
                }
            }
        }
        __syncthreads();
    }

    // ---- epilogue: divide by row sums, write [B, S, D] f32 ----
    #pragma unroll
    for (int mt = 0; mt < 2; ++mt) {
        const float inv0 = 1.0f / lsum[mt][0];
        const float inv1 = 1.0f / lsum[mt][1];
        const int srow = q0 + wid * 32 + mt * 16 + g;
        #pragma unroll
        for (int nv = 0; nv < 8; ++nv) {
            const int d0 = h * 64 + nv * 8 + 2 * t;
            float2 v0, v1;
            v0.x = o[mt][nv][0] * inv0; v0.y = o[mt][nv][1] * inv0;
            v1.x = o[mt][nv][2] * inv1; v1.y = o[mt][nv][3] * inv1;
            *(float2*)&out[((long long)(b * kS + srow)) * kD + d0] = v0;
            *(float2*)&out[((long long)(b * kS + srow + 8)) * kD + d0] = v1;
        }
    }
}

// ======================= launch =======================
extern "C" void kernel_launch(void* const* d_in, const int* in_sizes, int n_in,
                              void* d_out, int out_size)
{
    (void)in_sizes; (void)n_in; (void)out_size;
    const float* X    = (const float*)d_in[0];
    const float* mask = (const float*)d_in[1];
    const float* Wq   = (const float*)d_in[2];
    const float* bq   = (const float*)d_in[3];
    const float* Wk   = (const float*)d_in[4];
    const float* bk   = (const float*)d_in[5];
    const float* Wv   = (const float*)d_in[6];
    const float* bv   = (const float*)d_in[7];
    float* out = (float*)d_out;

    cudaFuncSetAttribute(qkv_kernel, cudaFuncAttributeMaxDynamicSharedMemorySize,
                         GEMM_SMEM_BYTES);
    cudaFuncSetAttribute(attn_kernel, cudaFuncAttributeMaxDynamicSharedMemorySize,
                         ATTN_SMEM_BYTES);

    prep_wt_kernel<<<dim3(32, 32, 3), 256>>>(Wq, Wk, Wv);
    prep_x_kernel<<<1024, 256>>>(X);
    qkv_kernel<<<dim3(kD / 128, kM / 128, 3), 256, GEMM_SMEM_BYTES>>>(bq, bk, bv);
    attn_kernel<<<dim3(kS / 128, kB * kH), 128, ATTN_SMEM_BYTES>>>(mask, out);
}